// round 1
// baseline (speedup 1.0000x reference)
#include <cuda_runtime.h>
#include <math.h>
#include <stdint.h>

#define N_NODES 30000
#define FDIM    256
#define E_EDGES 480000
#define T_EDGES (E_EDGES + N_NODES)   // 510000 (edges + self loops)
#define HEADS   4
#define HDIM    32
#define HH      128                    // HEADS*HDIM
#define NUM_LABEL 6
#define RN      16                     // ROUTE_NODES
#define PCOUT   8
#define NEG_SLOPE 0.2f
#define BN_EPS  1e-5f

#define OUT_OFF_LOSS (N_NODES * NUM_LABEL)          // 180000
#define OUT_OFF_FEAT (OUT_OFF_LOSS + 1)             // 180001

// ---------------- scratch (static device globals; no runtime alloc) --------
__device__ float g_sum[FDIM];
__device__ float g_sumsq[FDIM];
__device__ float g_scale[FDIM];
__device__ float g_shift[FDIM];
__device__ float g_Wc[FDIM * 256];
__device__ float g_bc[256];
__device__ float g_C[(size_t)N_NODES * 256];        // [0:128)=hidden, [128:256)=xt
__device__ float g_si[N_NODES * HEADS];
__device__ float g_sj[N_NODES * HEADS];
__device__ int   g_deg[N_NODES];
__device__ int   g_off[N_NODES + 1];
__device__ int   g_cur[N_NODES];
__device__ int   g_eid[T_EDGES];
__device__ float g_alpha[(size_t)T_EDGES * HEADS];
__device__ float g_gat[(size_t)N_NODES * HH];       // relu(aggr/den + b_gat)

// ---------------- init ------------------------------------------------------
__global__ void init_kernel(float* out) {
    int i = blockIdx.x * blockDim.x + threadIdx.x;
    if (i < FDIM)                 g_sum[i] = 0.f;
    else if (i < 2 * FDIM)        g_sumsq[i - FDIM] = 0.f;
    else if (i < 2 * FDIM + N_NODES) g_deg[i - 2 * FDIM] = 0;
    else if (i == 2 * FDIM + N_NODES) out[OUT_OFF_LOSS] = 0.f;
}

// ---------------- BN stats / fold -------------------------------------------
__global__ void bn_stats_kernel(const float* __restrict__ x) {
    int col = threadIdx.x;
    int r0 = blockIdx.x * 125;
    float s = 0.f, s2 = 0.f;
    #pragma unroll 5
    for (int r = 0; r < 125; r++) {
        float v = x[(size_t)(r0 + r) * FDIM + col];
        s += v; s2 += v * v;
    }
    atomicAdd(&g_sum[col], s);
    atomicAdd(&g_sumsq[col], s2);
}

__global__ void bn_fin_kernel(const float* __restrict__ gamma,
                              const float* __restrict__ beta) {
    int t = threadIdx.x;
    float mean = g_sum[t] / (float)N_NODES;
    float var  = g_sumsq[t] / (float)N_NODES - mean * mean;
    float sc = gamma[t] * rsqrtf(var + BN_EPS);
    g_scale[t] = sc;
    g_shift[t] = beta[t] - mean * sc;
}

__global__ void fold_w_kernel(const float* __restrict__ W_lin,
                              const float* __restrict__ W_gat) {
    int k = blockIdx.x, j = threadIdx.x;
    float wv = (j < 128) ? W_lin[k * 128 + j] : W_gat[k * 128 + j - 128];
    g_Wc[k * 256 + j] = g_scale[k] * wv;
}

__global__ void fold_b_kernel(const float* __restrict__ W_lin,
                              const float* __restrict__ W_gat,
                              const float* __restrict__ b_lin) {
    int j = threadIdx.x;
    float acc = (j < 128) ? b_lin[j] : 0.f;
    for (int k = 0; k < FDIM; k++) {
        float wv = (j < 128) ? W_lin[k * 128 + j] : W_gat[k * 128 + j - 128];
        acc += g_shift[k] * wv;
    }
    g_bc[j] = acc;
}

// ---------------- GEMM: C = x @ Wc + bc  (M=30000, N=256, K=256) ------------
#define BM 64
#define BN 64
#define BK 16
__global__ __launch_bounds__(256) void gemm_kernel(const float* __restrict__ x) {
    __shared__ float As[BK][BM + 4];
    __shared__ float Bs[BK][BN];
    int tid = threadIdx.x;
    int row0 = blockIdx.y * BM;
    int col0 = blockIdx.x * BN;
    int tx = tid & 15, ty = tid >> 4;

    float acc[4][4];
    #pragma unroll
    for (int i = 0; i < 4; i++)
        #pragma unroll
        for (int j = 0; j < 4; j++) acc[i][j] = 0.f;

    int arow = tid >> 2;          // 0..63
    int akc  = (tid & 3) * 4;     // 0,4,8,12
    int bk   = tid >> 4;          // 0..15
    int bcc  = (tid & 15) * 4;

    for (int k0 = 0; k0 < FDIM; k0 += BK) {
        float4 av = make_float4(0.f, 0.f, 0.f, 0.f);
        int gr = row0 + arow;
        if (gr < N_NODES)
            av = *reinterpret_cast<const float4*>(&x[(size_t)gr * FDIM + k0 + akc]);
        As[akc + 0][arow] = av.x;
        As[akc + 1][arow] = av.y;
        As[akc + 2][arow] = av.z;
        As[akc + 3][arow] = av.w;
        float4 bv = *reinterpret_cast<const float4*>(&g_Wc[(k0 + bk) * 256 + col0 + bcc]);
        *reinterpret_cast<float4*>(&Bs[bk][bcc]) = bv;
        __syncthreads();
        #pragma unroll
        for (int kk = 0; kk < BK; kk++) {
            float4 a4 = *reinterpret_cast<const float4*>(&As[kk][ty * 4]);
            float4 b4 = *reinterpret_cast<const float4*>(&Bs[kk][tx * 4]);
            float aa[4] = {a4.x, a4.y, a4.z, a4.w};
            float bb[4] = {b4.x, b4.y, b4.z, b4.w};
            #pragma unroll
            for (int i = 0; i < 4; i++)
                #pragma unroll
                for (int j = 0; j < 4; j++) acc[i][j] += aa[i] * bb[j];
        }
        __syncthreads();
    }
    #pragma unroll
    for (int i = 0; i < 4; i++) {
        int gr = row0 + ty * 4 + i;
        if (gr < N_NODES) {
            #pragma unroll
            for (int j = 0; j < 4; j++) {
                int gc = col0 + tx * 4 + j;
                g_C[(size_t)gr * 256 + gc] = acc[i][j] + g_bc[gc];
            }
        }
    }
}

// ---------------- per-node attention dots -----------------------------------
__global__ void dots_kernel(const float* __restrict__ att) {
    int w = (blockIdx.x * blockDim.x + threadIdx.x) >> 5;
    int lane = threadIdx.x & 31;
    if (w >= N_NODES) return;
    #pragma unroll
    for (int h = 0; h < HEADS; h++) {
        float xv = g_C[(size_t)w * 256 + 128 + h * 32 + lane];
        float si = xv * att[h * 64 + lane];
        float sj = xv * att[h * 64 + 32 + lane];
        #pragma unroll
        for (int d = 16; d > 0; d >>= 1) {
            si += __shfl_xor_sync(0xffffffffu, si, d);
            sj += __shfl_xor_sync(0xffffffffu, sj, d);
        }
        if (lane == 0) { g_si[w * 4 + h] = si; g_sj[w * 4 + h] = sj; }
    }
}

// ---------------- CSR build --------------------------------------------------
__global__ void deg_kernel(const int* __restrict__ dst) {
    int e = blockIdx.x * blockDim.x + threadIdx.x;
    if (e >= T_EDGES) return;
    int d = (e < E_EDGES) ? dst[e] : (e - E_EDGES);
    atomicAdd(&g_deg[d], 1);
}

__global__ void scan_kernel() {
    __shared__ int sh[1024];
    int tid = threadIdx.x;
    int carry = 0;
    const int CH = (N_NODES + 1023) / 1024;
    for (int c = 0; c < CH; c++) {
        int i = c * 1024 + tid;
        int v = (i < N_NODES) ? g_deg[i] : 0;
        sh[tid] = v;
        __syncthreads();
        for (int d = 1; d < 1024; d <<= 1) {
            int t = (tid >= d) ? sh[tid - d] : 0;
            __syncthreads();
            sh[tid] += t;
            __syncthreads();
        }
        if (i < N_NODES) g_off[i] = carry + sh[tid] - v;
        carry += sh[1023];
        __syncthreads();
    }
    if (tid == 0) g_off[N_NODES] = carry;
}

__global__ void curcopy_kernel() {
    int n = blockIdx.x * blockDim.x + threadIdx.x;
    if (n < N_NODES) g_cur[n] = g_off[n];
}

__global__ void scatter_kernel(const int* __restrict__ dst) {
    int e = blockIdx.x * blockDim.x + threadIdx.x;
    if (e >= T_EDGES) return;
    int d = (e < E_EDGES) ? dst[e] : (e - E_EDGES);
    int pos = atomicAdd(&g_cur[d], 1);
    g_eid[pos] = e;
}

// ---------------- edge alpha (leaky) -----------------------------------------
__global__ void alpha_kernel(const int* __restrict__ src,
                             const int* __restrict__ dst) {
    int e = blockIdx.x * blockDim.x + threadIdx.x;
    if (e >= T_EDGES) return;
    int s, d;
    if (e < E_EDGES) { s = src[e]; d = dst[e]; }
    else             { s = d = e - E_EDGES; }
    #pragma unroll
    for (int h = 0; h < HEADS; h++) {
        float a = g_si[d * 4 + h] + g_sj[s * 4 + h];
        a = (a >= 0.f) ? a : NEG_SLOPE * a;
        g_alpha[(size_t)e * 4 + h] = a;
    }
}

// ---------------- segment softmax + aggregation (warp per node-head) ---------
__global__ __launch_bounds__(256) void aggr_kernel(const int* __restrict__ src,
                                                   const float* __restrict__ b_gat) {
    int gw = (blockIdx.x * 256 + threadIdx.x) >> 5;
    int lane = threadIdx.x & 31;
    if (gw >= N_NODES * HEADS) return;
    int n = gw >> 2, h = gw & 3;
    int beg = g_off[n], end = g_off[n + 1];

    float m = -1e30f;
    for (int j = beg + lane; j < end; j += 32)
        m = fmaxf(m, g_alpha[(size_t)g_eid[j] * 4 + h]);
    #pragma unroll
    for (int d = 16; d > 0; d >>= 1)
        m = fmaxf(m, __shfl_xor_sync(0xffffffffu, m, d));

    float den = 0.f, acc = 0.f;
    for (int j = beg; j < end; j++) {
        int e = g_eid[j];
        float a = __expf(g_alpha[(size_t)e * 4 + h] - m);
        int s = (e < E_EDGES) ? src[e] : (e - E_EDGES);
        acc += a * g_C[(size_t)s * 256 + 128 + h * 32 + lane];
        den += a;
    }
    float r = acc / (den + 1e-16f) + b_gat[h * 32 + lane];
    g_gat[(size_t)n * HH + h * 32 + lane] = fmaxf(r, 0.f);
}

// ---------------- capsule + routing (warp per node) ---------------------------
#define CWARPS 12
#define CAP_SMEM_FLOATS (24576 + 512 + 16 + CWARPS*264 + CWARPS*128 + CWARPS*96)

__global__ __launch_bounds__(CWARPS * 32, 1)
void capsule_kernel(const float* __restrict__ Wp, const float* __restrict__ bp,
                    const float* __restrict__ route_w, const int* __restrict__ y,
                    float* __restrict__ out) {
    extern __shared__ float sh[];
    float* rw  = sh;                       // 24576 route_w
    float* wps = rw + 24576;               // 512
    float* bps = wps + 512;                // 16
    float* xcs = bps + 16;                 // CWARPS * 264 (8 x 33 padded)
    float* us  = xcs + CWARPS * 264;       // CWARPS * 128
    float* lgs = us  + CWARPS * 128;       // CWARPS * 96
    __shared__ float blockLoss;

    int tid = threadIdx.x, lane = tid & 31, w = tid >> 5;
    for (int i = tid; i < 24576; i += CWARPS * 32) rw[i] = route_w[i];
    for (int i = tid; i < 512; i += CWARPS * 32) wps[i] = Wp[i];
    if (tid < 16) bps[tid] = bp[tid];
    if (tid == 0) blockLoss = 0.f;
    __syncthreads();

    float* xcw = xcs + w * 264;
    float* uw  = us  + w * 128;
    float* lgw = lgs + w * 96;

    int gw = blockIdx.x * CWARPS + w;
    int nstride = gridDim.x * CWARPS;

    for (int n = gw; n < N_NODES; n += nstride) {
        // ---- xc = relu(concat(gat, hidden)), staged per warp
        #pragma unroll
        for (int r = 0; r < 8; r++) {
            float v = (r < 4)
                ? g_gat[(size_t)n * HH + r * 32 + lane]
                : fmaxf(g_C[(size_t)n * 256 + (r - 4) * 32 + lane], 0.f);
            xcw[r * 33 + lane] = v;
        }
        __syncwarp();

        // ---- primary capsules: pc -> squash -> u (shared)
        #pragma unroll
        for (int q = 0; q < 4; q++) {
            int idx = lane + 32 * q;
            int c = idx >> 6, r = (idx >> 3) & 7, o = idx & 7;
            float acc = bps[c * 8 + o];
            #pragma unroll
            for (int hh = 0; hh < 32; hh++)
                acc += xcw[r * 33 + hh] * wps[(c * 32 + hh) * 8 + o];
            float t = acc * acc;
            t += __shfl_xor_sync(0xffffffffu, t, 1);
            t += __shfl_xor_sync(0xffffffffu, t, 2);
            t += __shfl_xor_sync(0xffffffffu, t, 4);
            float uv = acc * t / ((1.f + t) * sqrtf(t));
            uw[idx] = uv;
        }
        __syncwarp();

        // ---- priors[c2][rr][o=lane], 96 registers per lane
        float pr[96];
        #pragma unroll
        for (int rr = 0; rr < 16; rr++) {
            float u0 = uw[rr*8+0], u1 = uw[rr*8+1], u2 = uw[rr*8+2], u3 = uw[rr*8+3];
            float u4 = uw[rr*8+4], u5 = uw[rr*8+5], u6 = uw[rr*8+6], u7 = uw[rr*8+7];
            #pragma unroll
            for (int c2 = 0; c2 < 6; c2++) {
                const float* wv = &rw[((c2 * 16 + rr) * 8) * 32 + lane];
                float a = u0 * wv[0]   + u1 * wv[32]  + u2 * wv[64]  + u3 * wv[96]
                        + u4 * wv[128] + u5 * wv[160] + u6 * wv[192] + u7 * wv[224];
                pr[c2 * 16 + rr] = a;
            }
        }

        // ---- dynamic routing (3 iters)
        for (int p = lane; p < 96; p += 32) lgw[p] = 0.f;
        __syncwarp();

        float vout[6], normc[6];
        for (int it = 0; it < 3; it++) {
            #pragma unroll
            for (int c = 0; c < 6; c++) {
                float lg[16];
                #pragma unroll
                for (int r = 0; r < 16; r++) lg[r] = lgw[c * 16 + r];
                float mx = lg[0];
                #pragma unroll
                for (int r = 1; r < 16; r++) mx = fmaxf(mx, lg[r]);
                float sm = 0.f;
                #pragma unroll
                for (int r = 0; r < 16; r++) { lg[r] = __expf(lg[r] - mx); sm += lg[r]; }
                float inv = 1.f / sm;
                float vv = 0.f;
                #pragma unroll
                for (int r = 0; r < 16; r++) vv += lg[r] * pr[c * 16 + r];
                vv *= inv;
                float t = vv * vv;
                t += __shfl_xor_sync(0xffffffffu, t, 1);
                t += __shfl_xor_sync(0xffffffffu, t, 2);
                t += __shfl_xor_sync(0xffffffffu, t, 4);
                t += __shfl_xor_sync(0xffffffffu, t, 8);
                t += __shfl_xor_sync(0xffffffffu, t, 16);
                float sc = t / ((1.f + t) * sqrtf(t));
                vout[c]  = vv * sc;
                normc[c] = t / (1.f + t);
            }
            if (it < 2) {
                #pragma unroll
                for (int c = 0; c < 6; c++) {
                    #pragma unroll
                    for (int r = 0; r < 16; r++) {
                        float t = pr[c * 16 + r] * vout[c];
                        t += __shfl_xor_sync(0xffffffffu, t, 1);
                        t += __shfl_xor_sync(0xffffffffu, t, 2);
                        t += __shfl_xor_sync(0xffffffffu, t, 4);
                        t += __shfl_xor_sync(0xffffffffu, t, 8);
                        t += __shfl_xor_sync(0xffffffffu, t, 16);
                        if (lane == 0) lgw[c * 16 + r] += t;
                    }
                }
                __syncwarp();
            }
        }

        // ---- outputs
        #pragma unroll
        for (int c = 0; c < 6; c++)
            out[OUT_OFF_FEAT + (size_t)n * (NUM_LABEL * HDIM) + c * 32 + lane] = vout[c];

        if (lane == 0) {
            float mx = normc[0];
            #pragma unroll
            for (int c = 1; c < 6; c++) mx = fmaxf(mx, normc[c]);
            float sm = 0.f;
            #pragma unroll
            for (int c = 0; c < 6; c++) sm += __expf(normc[c] - mx);
            float lse = mx + logf(sm);
            int yv = y[n];
            float sel = 0.f;
            #pragma unroll
            for (int c = 0; c < 6; c++) {
                out[(size_t)n * 6 + c] = normc[c];
                if (c == yv) sel = normc[c];
            }
            atomicAdd(&blockLoss, lse - sel);
        }
    }
    __syncthreads();
    if (tid == 0) atomicAdd(&out[OUT_OFF_LOSS], blockLoss / (float)N_NODES);
}

// ---------------- launch -----------------------------------------------------
extern "C" void kernel_launch(void* const* d_in, const int* in_sizes, int n_in,
                              void* d_out, int out_size) {
    const float* x       = (const float*)d_in[0];
    const float* gamma   = (const float*)d_in[1];
    const float* beta    = (const float*)d_in[2];
    const float* W_lin   = (const float*)d_in[3];
    const float* b_lin   = (const float*)d_in[4];
    const float* W_gat   = (const float*)d_in[5];
    const float* att     = (const float*)d_in[6];
    const float* b_gat   = (const float*)d_in[7];
    const float* Wp      = (const float*)d_in[8];
    const float* bp      = (const float*)d_in[9];
    const float* route_w = (const float*)d_in[10];
    const int*   eidx    = (const int*)d_in[11];
    const int*   y       = (const int*)d_in[12];
    float* out = (float*)d_out;

    const int* src = eidx;
    const int* dst = eidx + E_EDGES;

    init_kernel<<<(2 * FDIM + N_NODES + 256) / 256, 256>>>(out);
    bn_stats_kernel<<<240, 256>>>(x);
    bn_fin_kernel<<<1, 256>>>(gamma, beta);
    fold_w_kernel<<<256, 256>>>(W_lin, W_gat);
    fold_b_kernel<<<1, 256>>>(W_lin, W_gat, b_lin);

    gemm_kernel<<<dim3(256 / BN, (N_NODES + BM - 1) / BM), 256>>>(x);

    dots_kernel<<<(N_NODES * 32 + 255) / 256, 256>>>(att);
    deg_kernel<<<(T_EDGES + 255) / 256, 256>>>(dst);
    scan_kernel<<<1, 1024>>>();
    curcopy_kernel<<<(N_NODES + 255) / 256, 256>>>();
    scatter_kernel<<<(T_EDGES + 255) / 256, 256>>>(dst);
    alpha_kernel<<<(T_EDGES + 255) / 256, 256>>>(src, dst);
    aggr_kernel<<<(N_NODES * HEADS) / 8, 256>>>(src, b_gat);

    static const size_t cap_smem = (size_t)CAP_SMEM_FLOATS * sizeof(float);
    cudaFuncSetAttribute(capsule_kernel,
                         cudaFuncAttributeMaxDynamicSharedMemorySize,
                         (int)cap_smem);
    capsule_kernel<<<148, CWARPS * 32, cap_smem>>>(Wp, bp, route_w, y, out);
}

// round 2
// speedup vs baseline: 1.8125x; 1.8125x over previous
#include <cuda_runtime.h>
#include <cuda_bf16.h>
#include <math.h>
#include <stdint.h>

#define N_NODES 30000
#define FDIM    256
#define E_EDGES 480000
#define T_EDGES (E_EDGES + N_NODES)   // 510000
#define HEADS   4
#define HDIM    32
#define HH      128
#define NUM_LABEL 6
#define NEG_SLOPE 0.2f
#define BN_EPS  1e-5f

#define OUT_OFF_LOSS (N_NODES * NUM_LABEL)
#define OUT_OFF_FEAT (OUT_OFF_LOSS + 1)

// ---------------- scratch ----------------------------------------------------
__device__ float g_sum[FDIM];
__device__ float g_sumsq[FDIM];
__device__ float g_scale[FDIM];
__device__ float g_shift[FDIM];
__device__ __nv_bfloat16 g_Wb[768 * 256];           // [hi | lo | hi] x 256 cols
__device__ float g_bc[256];
__device__ float g_C[(size_t)N_NODES * 256];
__device__ float g_si[N_NODES * HEADS];
__device__ float g_sj[N_NODES * HEADS];
__device__ int   g_deg[N_NODES];
__device__ int   g_off[N_NODES + 1];
__device__ int   g_cur[N_NODES];
__device__ int   g_srcp[T_EDGES];                   // CSR-ordered src
__device__ float g_gat[(size_t)N_NODES * HH];

// ---------------- init --------------------------------------------------------
__global__ void init_kernel(float* out) {
    int i = blockIdx.x * blockDim.x + threadIdx.x;
    if (i < FDIM)                 g_sum[i] = 0.f;
    else if (i < 2 * FDIM)        g_sumsq[i - FDIM] = 0.f;
    else if (i < 2 * FDIM + N_NODES) g_deg[i - 2 * FDIM] = 0;
    else if (i == 2 * FDIM + N_NODES) out[OUT_OFF_LOSS] = 0.f;
}

// ---------------- BN stats / fold ---------------------------------------------
__global__ void bn_stats_kernel(const float* __restrict__ x) {
    int col = threadIdx.x;
    int r0 = blockIdx.x * 125;
    float s = 0.f, s2 = 0.f;
    #pragma unroll 5
    for (int r = 0; r < 125; r++) {
        float v = x[(size_t)(r0 + r) * FDIM + col];
        s += v; s2 += v * v;
    }
    atomicAdd(&g_sum[col], s);
    atomicAdd(&g_sumsq[col], s2);
}

__global__ void bn_fin_kernel(const float* __restrict__ gamma,
                              const float* __restrict__ beta) {
    int t = threadIdx.x;
    float mean = g_sum[t] / (float)N_NODES;
    float var  = g_sumsq[t] / (float)N_NODES - mean * mean;
    float sc = gamma[t] * rsqrtf(var + BN_EPS);
    g_scale[t] = sc;
    g_shift[t] = beta[t] - mean * sc;
}

// W' = scale .* [W_lin|W_gat]; split into bf16 hi/lo; layout K-tripled [hi|lo|hi]
__global__ void fold_w_kernel(const float* __restrict__ W_lin,
                              const float* __restrict__ W_gat) {
    int k = blockIdx.x, n = threadIdx.x;
    float wv = (n < 128) ? W_lin[k * 128 + n] : W_gat[k * 128 + n - 128];
    float w = g_scale[k] * wv;
    __nv_bfloat16 hi = __float2bfloat16(w);
    __nv_bfloat16 lo = __float2bfloat16(w - __bfloat162float(hi));
    g_Wb[k * 256 + n]         = hi;
    g_Wb[(k + 256) * 256 + n] = lo;
    g_Wb[(k + 512) * 256 + n] = hi;
}

__global__ void fold_b_kernel(const float* __restrict__ W_lin,
                              const float* __restrict__ W_gat,
                              const float* __restrict__ b_lin) {
    __shared__ float red[256];
    int j = blockIdx.x, k = threadIdx.x;
    float wv = (j < 128) ? W_lin[k * 128 + j] : W_gat[k * 128 + j - 128];
    red[k] = g_shift[k] * wv;
    __syncthreads();
    for (int d = 128; d > 0; d >>= 1) {
        if (k < d) red[k] += red[k + d];
        __syncthreads();
    }
    if (k == 0) g_bc[j] = red[0] + ((j < 128) ? b_lin[j] : 0.f);
}

// ---------------- GEMM: bf16 split mma.sync, M=30000 N=256 Kv=768 -------------
#define GSTEPS 48

__global__ __launch_bounds__(256) void gemm_mma_kernel(const float* __restrict__ x) {
    __shared__ __align__(16) char As[2][128 * 48];   // 128 rows x 16 bf16 (pitch 48B)
    __shared__ __align__(16) char Bs[2][16 * 272];   // 16 k-rows x 128 bf16 (pitch 272B)
    __shared__ float bcs[128];

    int tid = threadIdx.x;
    int lane = tid & 31, wid = tid >> 5;
    int wm = wid >> 2, wn = wid & 3;                  // 2 x 4 warp grid
    int row0 = blockIdx.y * 128, col0 = blockIdx.x * 128;

    if (tid < 128) bcs[tid] = g_bc[col0 + tid];

    int arow = tid >> 1, ac8 = (tid & 1) * 8;
    bool avalid = (row0 + arow) < N_NODES;
    const float* axp = x + (size_t)(row0 + arow) * 256 + ac8;
    int bkrow = tid >> 4, bnc = (tid & 15) * 8;
    const __nv_bfloat16* bwp = g_Wb + bkrow * 256 + col0 + bnc;

    float4 fa0, fa1; uint4 fb;

    // prefetch stage 0
    {
        if (avalid) { fa0 = *(const float4*)(axp); fa1 = *(const float4*)(axp + 4); }
        else { fa0 = make_float4(0,0,0,0); fa1 = fa0; }
        fb = *(const uint4*)(bwp);
    }
    // store stage 0
    {
        union { __nv_bfloat16 h[8]; uint4 u; } pk;
        float v[8] = {fa0.x,fa0.y,fa0.z,fa0.w,fa1.x,fa1.y,fa1.z,fa1.w};
        #pragma unroll
        for (int i = 0; i < 8; i++) pk.h[i] = __float2bfloat16(v[i]);   // seg0 = hi
        *(uint4*)(As[0] + arow * 48 + ac8 * 2) = pk.u;
        *(uint4*)(Bs[0] + bkrow * 272 + bnc * 2) = fb;
    }
    __syncthreads();

    float acc[4][4][4];
    #pragma unroll
    for (int a = 0; a < 4; a++)
        #pragma unroll
        for (int b = 0; b < 4; b++)
            #pragma unroll
            for (int c = 0; c < 4; c++) acc[a][b][c] = 0.f;

    for (int s = 0; s < GSTEPS; s++) {
        int cb = s & 1;
        // issue next-stage global loads (latency hidden behind compute)
        if (s + 1 < GSTEPS) {
            int sn = s + 1;
            int rk0 = (sn & 15) * 16;
            if (avalid) { fa0 = *(const float4*)(axp + rk0); fa1 = *(const float4*)(axp + rk0 + 4); }
            else { fa0 = make_float4(0,0,0,0); fa1 = fa0; }
            fb = *(const uint4*)(bwp + sn * 16 * 256);
        }

        // ---- compute stage s
        const char* Ab = As[cb];
        const char* Bb = Bs[cb];
        uint32_t afr[4][4];
        #pragma unroll
        for (int im = 0; im < 4; im++) {
            const char* p = Ab + (wm * 64 + im * 16 + (lane & 15)) * 48 + (lane >> 4) * 16;
            unsigned ad = (unsigned)__cvta_generic_to_shared(p);
            asm volatile("ldmatrix.sync.aligned.m8n8.x4.shared.b16 {%0,%1,%2,%3}, [%4];"
                : "=r"(afr[im][0]), "=r"(afr[im][1]), "=r"(afr[im][2]), "=r"(afr[im][3]) : "r"(ad));
        }
        uint32_t bfr[4][2];
        #pragma unroll
        for (int half = 0; half < 2; half++) {
            const char* p = Bb + (lane & 15) * 272 + (wn * 32 + half * 16 + (lane >> 4) * 8) * 2;
            unsigned ad = (unsigned)__cvta_generic_to_shared(p);
            uint32_t r0, r1, r2, r3;
            asm volatile("ldmatrix.sync.aligned.m8n8.x4.trans.shared.b16 {%0,%1,%2,%3}, [%4];"
                : "=r"(r0), "=r"(r1), "=r"(r2), "=r"(r3) : "r"(ad));
            bfr[half*2][0] = r0; bfr[half*2][1] = r1;
            bfr[half*2+1][0] = r2; bfr[half*2+1][1] = r3;
        }
        #pragma unroll
        for (int im = 0; im < 4; im++)
            #pragma unroll
            for (int in = 0; in < 4; in++) {
                asm volatile(
                    "mma.sync.aligned.m16n8k16.row.col.f32.bf16.bf16.f32 "
                    "{%0,%1,%2,%3}, {%4,%5,%6,%7}, {%8,%9}, {%0,%1,%2,%3};"
                    : "+f"(acc[im][in][0]), "+f"(acc[im][in][1]),
                      "+f"(acc[im][in][2]), "+f"(acc[im][in][3])
                    : "r"(afr[im][0]), "r"(afr[im][1]), "r"(afr[im][2]), "r"(afr[im][3]),
                      "r"(bfr[in][0]), "r"(bfr[in][1]));
            }

        // ---- store next stage
        if (s + 1 < GSTEPS) {
            int seg = (s + 1) >> 4;
            union { __nv_bfloat16 h[8]; uint4 u; } pk;
            float v[8] = {fa0.x,fa0.y,fa0.z,fa0.w,fa1.x,fa1.y,fa1.z,fa1.w};
            #pragma unroll
            for (int i = 0; i < 8; i++) {
                __nv_bfloat16 hb = __float2bfloat16(v[i]);
                if (seg == 2) hb = __float2bfloat16(v[i] - __bfloat162float(hb));
                pk.h[i] = hb;
            }
            *(uint4*)(As[cb ^ 1] + arow * 48 + ac8 * 2) = pk.u;
            *(uint4*)(Bs[cb ^ 1] + bkrow * 272 + bnc * 2) = fb;
        }
        __syncthreads();
    }

    // ---- epilogue
    #pragma unroll
    for (int im = 0; im < 4; im++) {
        int r = row0 + wm * 64 + im * 16 + (lane >> 2);
        #pragma unroll
        for (int in = 0; in < 4; in++) {
            int crel = wn * 32 + in * 8 + (lane & 3) * 2;
            int c = col0 + crel;
            if (r < N_NODES) {
                float2 v0 = make_float2(acc[im][in][0] + bcs[crel],
                                        acc[im][in][1] + bcs[crel + 1]);
                *(float2*)&g_C[(size_t)r * 256 + c] = v0;
            }
            if (r + 8 < N_NODES) {
                float2 v1 = make_float2(acc[im][in][2] + bcs[crel],
                                        acc[im][in][3] + bcs[crel + 1]);
                *(float2*)&g_C[(size_t)(r + 8) * 256 + c] = v1;
            }
        }
    }
}

// ---------------- per-node attention dots --------------------------------------
__global__ void dots_kernel(const float* __restrict__ att) {
    int w = (blockIdx.x * blockDim.x + threadIdx.x) >> 5;
    int lane = threadIdx.x & 31;
    if (w >= N_NODES) return;
    #pragma unroll
    for (int h = 0; h < HEADS; h++) {
        float xv = g_C[(size_t)w * 256 + 128 + h * 32 + lane];
        float si = xv * att[h * 64 + lane];
        float sj = xv * att[h * 64 + 32 + lane];
        #pragma unroll
        for (int d = 16; d > 0; d >>= 1) {
            si += __shfl_xor_sync(0xffffffffu, si, d);
            sj += __shfl_xor_sync(0xffffffffu, sj, d);
        }
        if (lane == 0) { g_si[w * 4 + h] = si; g_sj[w * 4 + h] = sj; }
    }
}

// ---------------- CSR build ------------------------------------------------------
__global__ void deg_kernel(const int* __restrict__ dst) {
    int e = blockIdx.x * blockDim.x + threadIdx.x;
    if (e >= T_EDGES) return;
    int d = (e < E_EDGES) ? dst[e] : (e - E_EDGES);
    atomicAdd(&g_deg[d], 1);
}

__global__ void scan_kernel() {
    __shared__ int wsum[32];
    int tid = threadIdx.x;
    int lane = tid & 31, wrp = tid >> 5;
    int carry = 0;
    const int CH = (N_NODES + 1023) / 1024;
    for (int c = 0; c < CH; c++) {
        int i = c * 1024 + tid;
        int v = (i < N_NODES) ? g_deg[i] : 0;
        int incl = v;
        #pragma unroll
        for (int d = 1; d < 32; d <<= 1) {
            int t = __shfl_up_sync(0xffffffffu, incl, d);
            if (lane >= d) incl += t;
        }
        if (lane == 31) wsum[wrp] = incl;
        __syncthreads();
        if (wrp == 0) {
            int wv = wsum[lane];
            #pragma unroll
            for (int d = 1; d < 32; d <<= 1) {
                int t = __shfl_up_sync(0xffffffffu, wv, d);
                if (lane >= d) wv += t;
            }
            wsum[lane] = wv;
        }
        __syncthreads();
        int base = (wrp > 0) ? wsum[wrp - 1] : 0;
        if (i < N_NODES) g_off[i] = carry + base + incl - v;
        carry += wsum[31];
        __syncthreads();
    }
    if (tid == 0) g_off[N_NODES] = carry;
}

__global__ void curcopy_kernel() {
    int n = blockIdx.x * blockDim.x + threadIdx.x;
    if (n < N_NODES) g_cur[n] = g_off[n];
}

__global__ void scatter_kernel(const int* __restrict__ src,
                               const int* __restrict__ dst) {
    int e = blockIdx.x * blockDim.x + threadIdx.x;
    if (e >= T_EDGES) return;
    int s, d;
    if (e < E_EDGES) { s = src[e]; d = dst[e]; }
    else             { s = d = e - E_EDGES; }
    int pos = atomicAdd(&g_cur[d], 1);
    g_srcp[pos] = s;
}

// ---------------- segment softmax + aggregation (warp per node-head) ------------
__global__ __launch_bounds__(256) void aggr_kernel(const float* __restrict__ b_gat) {
    int gw = (blockIdx.x * 256 + threadIdx.x) >> 5;
    int lane = threadIdx.x & 31;
    if (gw >= N_NODES * HEADS) return;
    int n = gw >> 2, h = gw & 3;
    int beg = g_off[n], end = g_off[n + 1];
    float si = g_si[n * 4 + h];

    float m = -1e30f;
    for (int j = beg + lane; j < end; j += 32) {
        int s = g_srcp[j];
        float a = si + g_sj[s * 4 + h];
        a = (a >= 0.f) ? a : NEG_SLOPE * a;
        m = fmaxf(m, a);
    }
    #pragma unroll
    for (int d = 16; d > 0; d >>= 1)
        m = fmaxf(m, __shfl_xor_sync(0xffffffffu, m, d));

    float den = 0.f, acc = 0.f;
    for (int j = beg; j < end; j++) {
        int s = g_srcp[j];
        float a = si + g_sj[s * 4 + h];
        a = (a >= 0.f) ? a : NEG_SLOPE * a;
        float e = __expf(a - m);
        acc += e * g_C[(size_t)s * 256 + 128 + h * 32 + lane];
        den += e;
    }
    float r = acc / (den + 1e-16f) + b_gat[h * 32 + lane];
    g_gat[(size_t)n * HH + h * 32 + lane] = fmaxf(r, 0.f);
}

// ---------------- capsule + routing (warp per node) ------------------------------
#define CWARPS 8
#define CAP_SMEM_FLOATS (24576 + 512 + 16 + CWARPS*264 + CWARPS*128 + CWARPS*96)

__global__ __launch_bounds__(CWARPS * 32, 1)
void capsule_kernel(const float* __restrict__ Wp, const float* __restrict__ bp,
                    const float* __restrict__ route_w, const int* __restrict__ y,
                    float* __restrict__ out) {
    extern __shared__ float sh[];
    float4* rw4 = (float4*)sh;             // 6144 float4 = 24576 floats
    float* wps = sh + 24576;               // 512
    float* bps = wps + 512;                // 16
    float* xcs = bps + 16;                 // CWARPS * 264
    float* us  = xcs + CWARPS * 264;       // CWARPS * 128
    float* lgs = us  + CWARPS * 128;       // CWARPS * 96
    __shared__ float blockLoss;

    int tid = threadIdx.x, lane = tid & 31, w = tid >> 5;

    // repack route_w: rw4[(pair*2+kq)*32 + lane] = {w[k..k+3] at o=lane}, k=4*kq
    for (int i4 = tid; i4 < 6144; i4 += CWARPS * 32) {
        int pair = i4 >> 6;
        int rem = i4 & 63;
        int kq = rem >> 5, ln = rem & 31;
        int base = (pair * 8 + kq * 4) * 32 + ln;
        rw4[i4] = make_float4(route_w[base], route_w[base + 32],
                              route_w[base + 64], route_w[base + 96]);
    }
    for (int i = tid; i < 512; i += CWARPS * 32) wps[i] = Wp[i];
    if (tid < 16) bps[tid] = bp[tid];
    if (tid == 0) blockLoss = 0.f;
    __syncthreads();

    float* xcw = xcs + w * 264;
    float* uw  = us  + w * 128;
    float* lgw = lgs + w * 96;

    int gw = blockIdx.x * CWARPS + w;
    int nstride = gridDim.x * CWARPS;

    for (int n = gw; n < N_NODES; n += nstride) {
        #pragma unroll
        for (int r = 0; r < 8; r++) {
            float v = (r < 4)
                ? g_gat[(size_t)n * HH + r * 32 + lane]
                : fmaxf(g_C[(size_t)n * 256 + (r - 4) * 32 + lane], 0.f);
            xcw[r * 33 + lane] = v;
        }
        __syncwarp();

        #pragma unroll
        for (int q = 0; q < 4; q++) {
            int idx = lane + 32 * q;
            int c = idx >> 6, r = (idx >> 3) & 7, o = idx & 7;
            float acc = bps[c * 8 + o];
            #pragma unroll
            for (int hh = 0; hh < 32; hh++)
                acc += xcw[r * 33 + hh] * wps[(c * 32 + hh) * 8 + o];
            float t = acc * acc;
            t += __shfl_xor_sync(0xffffffffu, t, 1);
            t += __shfl_xor_sync(0xffffffffu, t, 2);
            t += __shfl_xor_sync(0xffffffffu, t, 4);
            float uv = acc * t / ((1.f + t) * sqrtf(t));
            uw[idx] = uv;
        }
        __syncwarp();

        float pr[96];
        #pragma unroll
        for (int rr = 0; rr < 16; rr++) {
            float u0 = uw[rr*8+0], u1 = uw[rr*8+1], u2 = uw[rr*8+2], u3 = uw[rr*8+3];
            float u4 = uw[rr*8+4], u5 = uw[rr*8+5], u6 = uw[rr*8+6], u7 = uw[rr*8+7];
            #pragma unroll
            for (int c2 = 0; c2 < 6; c2++) {
                int pair = c2 * 16 + rr;
                float4 f0 = rw4[(pair * 2 + 0) * 32 + lane];
                float4 f1 = rw4[(pair * 2 + 1) * 32 + lane];
                pr[c2 * 16 + rr] =
                    u0 * f0.x + u1 * f0.y + u2 * f0.z + u3 * f0.w +
                    u4 * f1.x + u5 * f1.y + u6 * f1.z + u7 * f1.w;
            }
        }

        for (int p = lane; p < 96; p += 32) lgw[p] = 0.f;
        __syncwarp();

        float vout[6], normc[6];
        for (int it = 0; it < 3; it++) {
            #pragma unroll
            for (int c = 0; c < 6; c++) {
                float lg[16];
                #pragma unroll
                for (int r = 0; r < 16; r++) lg[r] = lgw[c * 16 + r];
                float mx = lg[0];
                #pragma unroll
                for (int r = 1; r < 16; r++) mx = fmaxf(mx, lg[r]);
                float sm = 0.f;
                #pragma unroll
                for (int r = 0; r < 16; r++) { lg[r] = __expf(lg[r] - mx); sm += lg[r]; }
                float inv = 1.f / sm;
                float vv = 0.f;
                #pragma unroll
                for (int r = 0; r < 16; r++) vv += lg[r] * pr[c * 16 + r];
                vv *= inv;
                float t = vv * vv;
                t += __shfl_xor_sync(0xffffffffu, t, 1);
                t += __shfl_xor_sync(0xffffffffu, t, 2);
                t += __shfl_xor_sync(0xffffffffu, t, 4);
                t += __shfl_xor_sync(0xffffffffu, t, 8);
                t += __shfl_xor_sync(0xffffffffu, t, 16);
                float sc = t / ((1.f + t) * sqrtf(t));
                vout[c]  = vv * sc;
                normc[c] = t / (1.f + t);
            }
            if (it < 2) {
                #pragma unroll
                for (int c = 0; c < 6; c++) {
                    #pragma unroll
                    for (int r = 0; r < 16; r++) {
                        float t = pr[c * 16 + r] * vout[c];
                        t += __shfl_xor_sync(0xffffffffu, t, 1);
                        t += __shfl_xor_sync(0xffffffffu, t, 2);
                        t += __shfl_xor_sync(0xffffffffu, t, 4);
                        t += __shfl_xor_sync(0xffffffffu, t, 8);
                        t += __shfl_xor_sync(0xffffffffu, t, 16);
                        if (lane == 0) lgw[c * 16 + r] += t;
                    }
                }
                __syncwarp();
            }
        }

        #pragma unroll
        for (int c = 0; c < 6; c++)
            out[OUT_OFF_FEAT + (size_t)n * (NUM_LABEL * HDIM) + c * 32 + lane] = vout[c];

        if (lane == 0) {
            float mx = normc[0];
            #pragma unroll
            for (int c = 1; c < 6; c++) mx = fmaxf(mx, normc[c]);
            float sm = 0.f;
            #pragma unroll
            for (int c = 0; c < 6; c++) sm += __expf(normc[c] - mx);
            float lse = mx + logf(sm);
            int yv = y[n];
            float sel = 0.f;
            #pragma unroll
            for (int c = 0; c < 6; c++) {
                out[(size_t)n * 6 + c] = normc[c];
                if (c == yv) sel = normc[c];
            }
            atomicAdd(&blockLoss, lse - sel);
        }
    }
    __syncthreads();
    if (tid == 0) atomicAdd(&out[OUT_OFF_LOSS], blockLoss / (float)N_NODES);
}

// ---------------- launch ---------------------------------------------------------
extern "C" void kernel_launch(void* const* d_in, const int* in_sizes, int n_in,
                              void* d_out, int out_size) {
    const float* x       = (const float*)d_in[0];
    const float* gamma   = (const float*)d_in[1];
    const float* beta    = (const float*)d_in[2];
    const float* W_lin   = (const float*)d_in[3];
    const float* b_lin   = (const float*)d_in[4];
    const float* W_gat   = (const float*)d_in[5];
    const float* att     = (const float*)d_in[6];
    const float* b_gat   = (const float*)d_in[7];
    const float* Wp      = (const float*)d_in[8];
    const float* bp      = (const float*)d_in[9];
    const float* route_w = (const float*)d_in[10];
    const int*   eidx    = (const int*)d_in[11];
    const int*   y       = (const int*)d_in[12];
    float* out = (float*)d_out;

    const int* src = eidx;
    const int* dst = eidx + E_EDGES;

    init_kernel<<<(2 * FDIM + N_NODES + 256) / 256, 256>>>(out);
    bn_stats_kernel<<<240, 256>>>(x);
    bn_fin_kernel<<<1, 256>>>(gamma, beta);
    fold_w_kernel<<<256, 256>>>(W_lin, W_gat);
    fold_b_kernel<<<256, 256>>>(W_lin, W_gat, b_lin);

    gemm_mma_kernel<<<dim3(2, (N_NODES + 127) / 128), 256>>>(x);

    dots_kernel<<<(N_NODES * 32 + 255) / 256, 256>>>(att);
    deg_kernel<<<(T_EDGES + 255) / 256, 256>>>(dst);
    scan_kernel<<<1, 1024>>>();
    curcopy_kernel<<<(N_NODES + 255) / 256, 256>>>();
    scatter_kernel<<<(T_EDGES + 255) / 256, 256>>>(src, dst);
    aggr_kernel<<<(N_NODES * HEADS + 7) / 8, 256>>>(b_gat);

    static const size_t cap_smem = (size_t)CAP_SMEM_FLOATS * sizeof(float);
    cudaFuncSetAttribute(capsule_kernel,
                         cudaFuncAttributeMaxDynamicSharedMemorySize,
                         (int)cap_smem);
    capsule_kernel<<<148, CWARPS * 32, cap_smem>>>(Wp, bp, route_w, y, out);
}

// round 3
// speedup vs baseline: 1.8138x; 1.0008x over previous
#include <cuda_runtime.h>
#include <cuda_bf16.h>
#include <math.h>
#include <stdint.h>

#define N_NODES 30000
#define FDIM    256
#define E_EDGES 480000
#define T_EDGES (E_EDGES + N_NODES)   // 510000
#define HEADS   4
#define HDIM    32
#define HH      128
#define NUM_LABEL 6
#define NEG_SLOPE 0.2f
#define BN_EPS  1e-5f

#define OUT_OFF_LOSS (N_NODES * NUM_LABEL)
#define OUT_OFF_FEAT (OUT_OFF_LOSS + 1)

// ---------------- scratch ----------------------------------------------------
__device__ float g_sum[FDIM];
__device__ float g_sumsq[FDIM];
__device__ float g_scale[FDIM];
__device__ float g_shift[FDIM];
__device__ __nv_bfloat16 g_Wb[768 * 256];           // [hi | lo | hi] x 256 cols
__device__ float g_bc[256];
__device__ float g_C[(size_t)N_NODES * 256];
__device__ float g_si[N_NODES * HEADS];
__device__ float g_sj[N_NODES * HEADS];
__device__ int   g_deg[N_NODES];
__device__ int   g_off[N_NODES + 1];
__device__ int   g_cur[N_NODES];
__device__ int   g_srcp[T_EDGES];                   // CSR-ordered src
__device__ float g_gat[(size_t)N_NODES * HH];

// ---------------- init --------------------------------------------------------
__global__ void init_kernel(float* out) {
    int i = blockIdx.x * blockDim.x + threadIdx.x;
    if (i < FDIM)                 g_sum[i] = 0.f;
    else if (i < 2 * FDIM)        g_sumsq[i - FDIM] = 0.f;
    else if (i < 2 * FDIM + N_NODES) g_deg[i - 2 * FDIM] = 0;
    else if (i == 2 * FDIM + N_NODES) out[OUT_OFF_LOSS] = 0.f;
}

// ---------------- BN stats / fold ---------------------------------------------
__global__ void bn_stats_kernel(const float* __restrict__ x) {
    int col = threadIdx.x;
    int r0 = blockIdx.x * 125;
    float s = 0.f, s2 = 0.f;
    #pragma unroll 5
    for (int r = 0; r < 125; r++) {
        float v = x[(size_t)(r0 + r) * FDIM + col];
        s += v; s2 += v * v;
    }
    atomicAdd(&g_sum[col], s);
    atomicAdd(&g_sumsq[col], s2);
}

__global__ void bn_fin_kernel(const float* __restrict__ gamma,
                              const float* __restrict__ beta) {
    int t = threadIdx.x;
    float mean = g_sum[t] / (float)N_NODES;
    float var  = g_sumsq[t] / (float)N_NODES - mean * mean;
    float sc = gamma[t] * rsqrtf(var + BN_EPS);
    g_scale[t] = sc;
    g_shift[t] = beta[t] - mean * sc;
}

// W' = scale .* [W_lin|W_gat]; split into bf16 hi/lo; layout K-tripled [hi|lo|hi]
__global__ void fold_w_kernel(const float* __restrict__ W_lin,
                              const float* __restrict__ W_gat) {
    int k = blockIdx.x, n = threadIdx.x;
    float wv = (n < 128) ? W_lin[k * 128 + n] : W_gat[k * 128 + n - 128];
    float w = g_scale[k] * wv;
    __nv_bfloat16 hi = __float2bfloat16(w);
    __nv_bfloat16 lo = __float2bfloat16(w - __bfloat162float(hi));
    g_Wb[k * 256 + n]         = hi;
    g_Wb[(k + 256) * 256 + n] = lo;
    g_Wb[(k + 512) * 256 + n] = hi;
}

__global__ void fold_b_kernel(const float* __restrict__ W_lin,
                              const float* __restrict__ W_gat,
                              const float* __restrict__ b_lin) {
    __shared__ float red[256];
    int j = blockIdx.x, k = threadIdx.x;
    float wv = (j < 128) ? W_lin[k * 128 + j] : W_gat[k * 128 + j - 128];
    red[k] = g_shift[k] * wv;
    __syncthreads();
    for (int d = 128; d > 0; d >>= 1) {
        if (k < d) red[k] += red[k + d];
        __syncthreads();
    }
    if (k == 0) g_bc[j] = red[0] + ((j < 128) ? b_lin[j] : 0.f);
}

// ---------------- GEMM: bf16 split mma.sync, M=30000 N=256 Kv=768 -------------
#define GSTEPS 48

__global__ __launch_bounds__(256) void gemm_mma_kernel(const float* __restrict__ x) {
    __shared__ __align__(16) char As[2][128 * 48];   // 128 rows x 16 bf16 (pitch 48B)
    __shared__ __align__(16) char Bs[2][16 * 272];   // 16 k-rows x 128 bf16 (pitch 272B)
    __shared__ float bcs[128];

    int tid = threadIdx.x;
    int lane = tid & 31, wid = tid >> 5;
    int wm = wid >> 2, wn = wid & 3;                  // 2 x 4 warp grid
    int row0 = blockIdx.y * 128, col0 = blockIdx.x * 128;

    if (tid < 128) bcs[tid] = g_bc[col0 + tid];

    int arow = tid >> 1, ac8 = (tid & 1) * 8;
    bool avalid = (row0 + arow) < N_NODES;
    const float* axp = x + (size_t)(row0 + arow) * 256 + ac8;
    int bkrow = tid >> 4, bnc = (tid & 15) * 8;
    const __nv_bfloat16* bwp = g_Wb + bkrow * 256 + col0 + bnc;

    float4 fa0, fa1; uint4 fb;

    // prefetch stage 0
    {
        if (avalid) { fa0 = *(const float4*)(axp); fa1 = *(const float4*)(axp + 4); }
        else { fa0 = make_float4(0,0,0,0); fa1 = fa0; }
        fb = *(const uint4*)(bwp);
    }
    // store stage 0
    {
        union { __nv_bfloat16 h[8]; uint4 u; } pk;
        float v[8] = {fa0.x,fa0.y,fa0.z,fa0.w,fa1.x,fa1.y,fa1.z,fa1.w};
        #pragma unroll
        for (int i = 0; i < 8; i++) pk.h[i] = __float2bfloat16(v[i]);   // seg0 = hi
        *(uint4*)(As[0] + arow * 48 + ac8 * 2) = pk.u;
        *(uint4*)(Bs[0] + bkrow * 272 + bnc * 2) = fb;
    }
    __syncthreads();

    float acc[4][4][4];
    #pragma unroll
    for (int a = 0; a < 4; a++)
        #pragma unroll
        for (int b = 0; b < 4; b++)
            #pragma unroll
            for (int c = 0; c < 4; c++) acc[a][b][c] = 0.f;

    for (int s = 0; s < GSTEPS; s++) {
        int cb = s & 1;
        // issue next-stage global loads (latency hidden behind compute)
        if (s + 1 < GSTEPS) {
            int sn = s + 1;
            int rk0 = (sn & 15) * 16;
            if (avalid) { fa0 = *(const float4*)(axp + rk0); fa1 = *(const float4*)(axp + rk0 + 4); }
            else { fa0 = make_float4(0,0,0,0); fa1 = fa0; }
            fb = *(const uint4*)(bwp + sn * 16 * 256);
        }

        // ---- compute stage s
        const char* Ab = As[cb];
        const char* Bb = Bs[cb];
        uint32_t afr[4][4];
        #pragma unroll
        for (int im = 0; im < 4; im++) {
            const char* p = Ab + (wm * 64 + im * 16 + (lane & 15)) * 48 + (lane >> 4) * 16;
            unsigned ad = (unsigned)__cvta_generic_to_shared(p);
            asm volatile("ldmatrix.sync.aligned.m8n8.x4.shared.b16 {%0,%1,%2,%3}, [%4];"
                : "=r"(afr[im][0]), "=r"(afr[im][1]), "=r"(afr[im][2]), "=r"(afr[im][3]) : "r"(ad));
        }
        uint32_t bfr[4][2];
        #pragma unroll
        for (int half = 0; half < 2; half++) {
            const char* p = Bb + (lane & 15) * 272 + (wn * 32 + half * 16 + (lane >> 4) * 8) * 2;
            unsigned ad = (unsigned)__cvta_generic_to_shared(p);
            uint32_t r0, r1, r2, r3;
            asm volatile("ldmatrix.sync.aligned.m8n8.x4.trans.shared.b16 {%0,%1,%2,%3}, [%4];"
                : "=r"(r0), "=r"(r1), "=r"(r2), "=r"(r3) : "r"(ad));
            bfr[half*2][0] = r0; bfr[half*2][1] = r1;
            bfr[half*2+1][0] = r2; bfr[half*2+1][1] = r3;
        }
        #pragma unroll
        for (int im = 0; im < 4; im++)
            #pragma unroll
            for (int in = 0; in < 4; in++) {
                asm volatile(
                    "mma.sync.aligned.m16n8k16.row.col.f32.bf16.bf16.f32 "
                    "{%0,%1,%2,%3}, {%4,%5,%6,%7}, {%8,%9}, {%0,%1,%2,%3};"
                    : "+f"(acc[im][in][0]), "+f"(acc[im][in][1]),
                      "+f"(acc[im][in][2]), "+f"(acc[im][in][3])
                    : "r"(afr[im][0]), "r"(afr[im][1]), "r"(afr[im][2]), "r"(afr[im][3]),
                      "r"(bfr[in][0]), "r"(bfr[in][1]));
            }

        // ---- store next stage
        if (s + 1 < GSTEPS) {
            int seg = (s + 1) >> 4;
            union { __nv_bfloat16 h[8]; uint4 u; } pk;
            float v[8] = {fa0.x,fa0.y,fa0.z,fa0.w,fa1.x,fa1.y,fa1.z,fa1.w};
            #pragma unroll
            for (int i = 0; i < 8; i++) {
                __nv_bfloat16 hb = __float2bfloat16(v[i]);
                if (seg == 2) hb = __float2bfloat16(v[i] - __bfloat162float(hb));
                pk.h[i] = hb;
            }
            *(uint4*)(As[cb ^ 1] + arow * 48 + ac8 * 2) = pk.u;
            *(uint4*)(Bs[cb ^ 1] + bkrow * 272 + bnc * 2) = fb;
        }
        __syncthreads();
    }

    // ---- epilogue
    #pragma unroll
    for (int im = 0; im < 4; im++) {
        int r = row0 + wm * 64 + im * 16 + (lane >> 2);
        #pragma unroll
        for (int in = 0; in < 4; in++) {
            int crel = wn * 32 + in * 8 + (lane & 3) * 2;
            int c = col0 + crel;
            if (r < N_NODES) {
                float2 v0 = make_float2(acc[im][in][0] + bcs[crel],
                                        acc[im][in][1] + bcs[crel + 1]);
                *(float2*)&g_C[(size_t)r * 256 + c] = v0;
            }
            if (r + 8 < N_NODES) {
                float2 v1 = make_float2(acc[im][in][2] + bcs[crel],
                                        acc[im][in][3] + bcs[crel + 1]);
                *(float2*)&g_C[(size_t)(r + 8) * 256 + c] = v1;
            }
        }
    }
}

// ---------------- per-node attention dots --------------------------------------
__global__ void dots_kernel(const float* __restrict__ att) {
    int w = (blockIdx.x * blockDim.x + threadIdx.x) >> 5;
    int lane = threadIdx.x & 31;
    if (w >= N_NODES) return;
    #pragma unroll
    for (int h = 0; h < HEADS; h++) {
        float xv = g_C[(size_t)w * 256 + 128 + h * 32 + lane];
        float si = xv * att[h * 64 + lane];
        float sj = xv * att[h * 64 + 32 + lane];
        #pragma unroll
        for (int d = 16; d > 0; d >>= 1) {
            si += __shfl_xor_sync(0xffffffffu, si, d);
            sj += __shfl_xor_sync(0xffffffffu, sj, d);
        }
        if (lane == 0) { g_si[w * 4 + h] = si; g_sj[w * 4 + h] = sj; }
    }
}

// ---------------- CSR build ------------------------------------------------------
__global__ void deg_kernel(const int* __restrict__ dst) {
    int e = blockIdx.x * blockDim.x + threadIdx.x;
    if (e >= T_EDGES) return;
    int d = (e < E_EDGES) ? dst[e] : (e - E_EDGES);
    atomicAdd(&g_deg[d], 1);
}

__global__ void scan_kernel() {
    __shared__ int wsum[32];
    int tid = threadIdx.x;
    int lane = tid & 31, wrp = tid >> 5;
    int carry = 0;
    const int CH = (N_NODES + 1023) / 1024;
    for (int c = 0; c < CH; c++) {
        int i = c * 1024 + tid;
        int v = (i < N_NODES) ? g_deg[i] : 0;
        int incl = v;
        #pragma unroll
        for (int d = 1; d < 32; d <<= 1) {
            int t = __shfl_up_sync(0xffffffffu, incl, d);
            if (lane >= d) incl += t;
        }
        if (lane == 31) wsum[wrp] = incl;
        __syncthreads();
        if (wrp == 0) {
            int wv = wsum[lane];
            #pragma unroll
            for (int d = 1; d < 32; d <<= 1) {
                int t = __shfl_up_sync(0xffffffffu, wv, d);
                if (lane >= d) wv += t;
            }
            wsum[lane] = wv;
        }
        __syncthreads();
        int base = (wrp > 0) ? wsum[wrp - 1] : 0;
        if (i < N_NODES) g_off[i] = carry + base + incl - v;
        carry += wsum[31];
        __syncthreads();
    }
    if (tid == 0) g_off[N_NODES] = carry;
}

__global__ void curcopy_kernel() {
    int n = blockIdx.x * blockDim.x + threadIdx.x;
    if (n < N_NODES) g_cur[n] = g_off[n];
}

__global__ void scatter_kernel(const int* __restrict__ src,
                               const int* __restrict__ dst) {
    int e = blockIdx.x * blockDim.x + threadIdx.x;
    if (e >= T_EDGES) return;
    int s, d;
    if (e < E_EDGES) { s = src[e]; d = dst[e]; }
    else             { s = d = e - E_EDGES; }
    int pos = atomicAdd(&g_cur[d], 1);
    g_srcp[pos] = s;
}

// ---------------- segment softmax + aggregation (warp per node-head) ------------
__global__ __launch_bounds__(256) void aggr_kernel(const float* __restrict__ b_gat) {
    int gw = (blockIdx.x * 256 + threadIdx.x) >> 5;
    int lane = threadIdx.x & 31;
    if (gw >= N_NODES * HEADS) return;
    int n = gw >> 2, h = gw & 3;
    int beg = g_off[n], end = g_off[n + 1];
    float si = g_si[n * 4 + h];

    float m = -1e30f;
    for (int j = beg + lane; j < end; j += 32) {
        int s = g_srcp[j];
        float a = si + g_sj[s * 4 + h];
        a = (a >= 0.f) ? a : NEG_SLOPE * a;
        m = fmaxf(m, a);
    }
    #pragma unroll
    for (int d = 16; d > 0; d >>= 1)
        m = fmaxf(m, __shfl_xor_sync(0xffffffffu, m, d));

    float den = 0.f, acc = 0.f;
    for (int j = beg; j < end; j++) {
        int s = g_srcp[j];
        float a = si + g_sj[s * 4 + h];
        a = (a >= 0.f) ? a : NEG_SLOPE * a;
        float e = __expf(a - m);
        acc += e * g_C[(size_t)s * 256 + 128 + h * 32 + lane];
        den += e;
    }
    float r = acc / (den + 1e-16f) + b_gat[h * 32 + lane];
    g_gat[(size_t)n * HH + h * 32 + lane] = fmaxf(r, 0.f);
}

// ---------------- capsule + routing (warp per node) ------------------------------
#define CWARPS 8
#define CAP_SMEM_FLOATS (24576 + 512 + 16 + CWARPS*264 + CWARPS*128 + CWARPS*96)

__global__ __launch_bounds__(CWARPS * 32, 1)
void capsule_kernel(const float* __restrict__ Wp, const float* __restrict__ bp,
                    const float* __restrict__ route_w, const int* __restrict__ y,
                    float* __restrict__ out) {
    extern __shared__ float sh[];
    float4* rw4 = (float4*)sh;             // 6144 float4 = 24576 floats
    float* wps = sh + 24576;               // 512
    float* bps = wps + 512;                // 16
    float* xcs = bps + 16;                 // CWARPS * 264
    float* us  = xcs + CWARPS * 264;       // CWARPS * 128
    float* lgs = us  + CWARPS * 128;       // CWARPS * 96
    __shared__ float blockLoss;

    int tid = threadIdx.x, lane = tid & 31, w = tid >> 5;

    // repack route_w: rw4[(pair*2+kq)*32 + lane] = {w[k..k+3] at o=lane}, k=4*kq
    for (int i4 = tid; i4 < 6144; i4 += CWARPS * 32) {
        int pair = i4 >> 6;
        int rem = i4 & 63;
        int kq = rem >> 5, ln = rem & 31;
        int base = (pair * 8 + kq * 4) * 32 + ln;
        rw4[i4] = make_float4(route_w[base], route_w[base + 32],
                              route_w[base + 64], route_w[base + 96]);
    }
    for (int i = tid; i < 512; i += CWARPS * 32) wps[i] = Wp[i];
    if (tid < 16) bps[tid] = bp[tid];
    if (tid == 0) blockLoss = 0.f;
    __syncthreads();

    float* xcw = xcs + w * 264;
    float* uw  = us  + w * 128;
    float* lgw = lgs + w * 96;

    int gw = blockIdx.x * CWARPS + w;
    int nstride = gridDim.x * CWARPS;

    for (int n = gw; n < N_NODES; n += nstride) {
        #pragma unroll
        for (int r = 0; r < 8; r++) {
            float v = (r < 4)
                ? g_gat[(size_t)n * HH + r * 32 + lane]
                : fmaxf(g_C[(size_t)n * 256 + (r - 4) * 32 + lane], 0.f);
            xcw[r * 33 + lane] = v;
        }
        __syncwarp();

        #pragma unroll
        for (int q = 0; q < 4; q++) {
            int idx = lane + 32 * q;
            int c = idx >> 6, r = (idx >> 3) & 7, o = idx & 7;
            float acc = bps[c * 8 + o];
            #pragma unroll
            for (int hh = 0; hh < 32; hh++)
                acc += xcw[r * 33 + hh] * wps[(c * 32 + hh) * 8 + o];
            float t = acc * acc;
            t += __shfl_xor_sync(0xffffffffu, t, 1);
            t += __shfl_xor_sync(0xffffffffu, t, 2);
            t += __shfl_xor_sync(0xffffffffu, t, 4);
            float uv = acc * t / ((1.f + t) * sqrtf(t));
            uw[idx] = uv;
        }
        __syncwarp();

        float pr[96];
        #pragma unroll
        for (int rr = 0; rr < 16; rr++) {
            float u0 = uw[rr*8+0], u1 = uw[rr*8+1], u2 = uw[rr*8+2], u3 = uw[rr*8+3];
            float u4 = uw[rr*8+4], u5 = uw[rr*8+5], u6 = uw[rr*8+6], u7 = uw[rr*8+7];
            #pragma unroll
            for (int c2 = 0; c2 < 6; c2++) {
                int pair = c2 * 16 + rr;
                float4 f0 = rw4[(pair * 2 + 0) * 32 + lane];
                float4 f1 = rw4[(pair * 2 + 1) * 32 + lane];
                pr[c2 * 16 + rr] =
                    u0 * f0.x + u1 * f0.y + u2 * f0.z + u3 * f0.w +
                    u4 * f1.x + u5 * f1.y + u6 * f1.z + u7 * f1.w;
            }
        }

        for (int p = lane; p < 96; p += 32) lgw[p] = 0.f;
        __syncwarp();

        float vout[6], normc[6];
        for (int it = 0; it < 3; it++) {
            #pragma unroll
            for (int c = 0; c < 6; c++) {
                float lg[16];
                #pragma unroll
                for (int r = 0; r < 16; r++) lg[r] = lgw[c * 16 + r];
                float mx = lg[0];
                #pragma unroll
                for (int r = 1; r < 16; r++) mx = fmaxf(mx, lg[r]);
                float sm = 0.f;
                #pragma unroll
                for (int r = 0; r < 16; r++) { lg[r] = __expf(lg[r] - mx); sm += lg[r]; }
                float inv = 1.f / sm;
                float vv = 0.f;
                #pragma unroll
                for (int r = 0; r < 16; r++) vv += lg[r] * pr[c * 16 + r];
                vv *= inv;
                float t = vv * vv;
                t += __shfl_xor_sync(0xffffffffu, t, 1);
                t += __shfl_xor_sync(0xffffffffu, t, 2);
                t += __shfl_xor_sync(0xffffffffu, t, 4);
                t += __shfl_xor_sync(0xffffffffu, t, 8);
                t += __shfl_xor_sync(0xffffffffu, t, 16);
                float sc = t / ((1.f + t) * sqrtf(t));
                vout[c]  = vv * sc;
                normc[c] = t / (1.f + t);
            }
            if (it < 2) {
                #pragma unroll
                for (int c = 0; c < 6; c++) {
                    #pragma unroll
                    for (int r = 0; r < 16; r++) {
                        float t = pr[c * 16 + r] * vout[c];
                        t += __shfl_xor_sync(0xffffffffu, t, 1);
                        t += __shfl_xor_sync(0xffffffffu, t, 2);
                        t += __shfl_xor_sync(0xffffffffu, t, 4);
                        t += __shfl_xor_sync(0xffffffffu, t, 8);
                        t += __shfl_xor_sync(0xffffffffu, t, 16);
                        if (lane == 0) lgw[c * 16 + r] += t;
                    }
                }
                __syncwarp();
            }
        }

        #pragma unroll
        for (int c = 0; c < 6; c++)
            out[OUT_OFF_FEAT + (size_t)n * (NUM_LABEL * HDIM) + c * 32 + lane] = vout[c];

        if (lane == 0) {
            float mx = normc[0];
            #pragma unroll
            for (int c = 1; c < 6; c++) mx = fmaxf(mx, normc[c]);
            float sm = 0.f;
            #pragma unroll
            for (int c = 0; c < 6; c++) sm += __expf(normc[c] - mx);
            float lse = mx + logf(sm);
            int yv = y[n];
            float sel = 0.f;
            #pragma unroll
            for (int c = 0; c < 6; c++) {
                out[(size_t)n * 6 + c] = normc[c];
                if (c == yv) sel = normc[c];
            }
            atomicAdd(&blockLoss, lse - sel);
        }
    }
    __syncthreads();
    if (tid == 0) atomicAdd(&out[OUT_OFF_LOSS], blockLoss / (float)N_NODES);
}

// ---------------- launch ---------------------------------------------------------
extern "C" void kernel_launch(void* const* d_in, const int* in_sizes, int n_in,
                              void* d_out, int out_size) {
    const float* x       = (const float*)d_in[0];
    const float* gamma   = (const float*)d_in[1];
    const float* beta    = (const float*)d_in[2];
    const float* W_lin   = (const float*)d_in[3];
    const float* b_lin   = (const float*)d_in[4];
    const float* W_gat   = (const float*)d_in[5];
    const float* att     = (const float*)d_in[6];
    const float* b_gat   = (const float*)d_in[7];
    const float* Wp      = (const float*)d_in[8];
    const float* bp      = (const float*)d_in[9];
    const float* route_w = (const float*)d_in[10];
    const int*   eidx    = (const int*)d_in[11];
    const int*   y       = (const int*)d_in[12];
    float* out = (float*)d_out;

    const int* src = eidx;
    const int* dst = eidx + E_EDGES;

    init_kernel<<<(2 * FDIM + N_NODES + 256) / 256, 256>>>(out);
    bn_stats_kernel<<<240, 256>>>(x);
    bn_fin_kernel<<<1, 256>>>(gamma, beta);
    fold_w_kernel<<<256, 256>>>(W_lin, W_gat);
    fold_b_kernel<<<256, 256>>>(W_lin, W_gat, b_lin);

    gemm_mma_kernel<<<dim3(2, (N_NODES + 127) / 128), 256>>>(x);

    dots_kernel<<<(N_NODES * 32 + 255) / 256, 256>>>(att);
    deg_kernel<<<(T_EDGES + 255) / 256, 256>>>(dst);
    scan_kernel<<<1, 1024>>>();
    curcopy_kernel<<<(N_NODES + 255) / 256, 256>>>();
    scatter_kernel<<<(T_EDGES + 255) / 256, 256>>>(src, dst);
    aggr_kernel<<<(N_NODES * HEADS + 7) / 8, 256>>>(b_gat);

    static const size_t cap_smem = (size_t)CAP_SMEM_FLOATS * sizeof(float);
    cudaFuncSetAttribute(capsule_kernel,
                         cudaFuncAttributeMaxDynamicSharedMemorySize,
                         (int)cap_smem);
    capsule_kernel<<<148, CWARPS * 32, cap_smem>>>(Wp, bp, route_w, y, out);
}

// round 4
// speedup vs baseline: 1.8205x; 1.0037x over previous
#include <cuda_runtime.h>
#include <cuda_bf16.h>
#include <math.h>
#include <stdint.h>

#define N_NODES 30000
#define FDIM    256
#define E_EDGES 480000
#define T_EDGES (E_EDGES + N_NODES)   // 510000
#define HEADS   4
#define HDIM    32
#define HH      128
#define NUM_LABEL 6
#define NEG_SLOPE 0.2f
#define BN_EPS  1e-5f

#define OUT_OFF_LOSS (N_NODES * NUM_LABEL)
#define OUT_OFF_FEAT (OUT_OFF_LOSS + 1)

// ---------------- scratch ----------------------------------------------------
__device__ float g_sum[FDIM];
__device__ float g_sumsq[FDIM];
__device__ float g_scale[FDIM];
__device__ float g_shift[FDIM];
__device__ __nv_bfloat16 g_Wb[768 * 256];           // [hi | lo | hi] x 256 cols
__device__ float g_bc[256];
__device__ float g_C[(size_t)N_NODES * 256];
__device__ float g_si[N_NODES * HEADS];
__device__ float g_sj[N_NODES * HEADS];
__device__ int   g_deg[N_NODES];
__device__ int   g_off[N_NODES + 1];
__device__ int   g_cur[N_NODES];
__device__ int   g_srcp[T_EDGES];                   // CSR-ordered src
__device__ float g_gat[(size_t)N_NODES * HH];

// ---------------- init --------------------------------------------------------
__global__ void init_kernel(float* out) {
    int i = blockIdx.x * blockDim.x + threadIdx.x;
    if (i < FDIM)                 g_sum[i] = 0.f;
    else if (i < 2 * FDIM)        g_sumsq[i - FDIM] = 0.f;
    else if (i < 2 * FDIM + N_NODES) g_deg[i - 2 * FDIM] = 0;
    else if (i == 2 * FDIM + N_NODES) out[OUT_OFF_LOSS] = 0.f;
}

// ---------------- BN stats / fold ---------------------------------------------
__global__ void bn_stats_kernel(const float* __restrict__ x) {
    int col = threadIdx.x;
    int r0 = blockIdx.x * 125;
    float s = 0.f, s2 = 0.f;
    #pragma unroll 5
    for (int r = 0; r < 125; r++) {
        float v = x[(size_t)(r0 + r) * FDIM + col];
        s += v; s2 += v * v;
    }
    atomicAdd(&g_sum[col], s);
    atomicAdd(&g_sumsq[col], s2);
}

__global__ void bn_fin_kernel(const float* __restrict__ gamma,
                              const float* __restrict__ beta) {
    int t = threadIdx.x;
    float mean = g_sum[t] / (float)N_NODES;
    float var  = g_sumsq[t] / (float)N_NODES - mean * mean;
    float sc = gamma[t] * rsqrtf(var + BN_EPS);
    g_scale[t] = sc;
    g_shift[t] = beta[t] - mean * sc;
}

// W' = scale .* [W_lin|W_gat]; split into bf16 hi/lo; layout K-tripled [hi|lo|hi]
__global__ void fold_w_kernel(const float* __restrict__ W_lin,
                              const float* __restrict__ W_gat) {
    int k = blockIdx.x, n = threadIdx.x;
    float wv = (n < 128) ? W_lin[k * 128 + n] : W_gat[k * 128 + n - 128];
    float w = g_scale[k] * wv;
    __nv_bfloat16 hi = __float2bfloat16(w);
    __nv_bfloat16 lo = __float2bfloat16(w - __bfloat162float(hi));
    g_Wb[k * 256 + n]         = hi;
    g_Wb[(k + 256) * 256 + n] = lo;
    g_Wb[(k + 512) * 256 + n] = hi;
}

__global__ void fold_b_kernel(const float* __restrict__ W_lin,
                              const float* __restrict__ W_gat,
                              const float* __restrict__ b_lin) {
    __shared__ float red[256];
    int j = blockIdx.x, k = threadIdx.x;
    float wv = (j < 128) ? W_lin[k * 128 + j] : W_gat[k * 128 + j - 128];
    red[k] = g_shift[k] * wv;
    __syncthreads();
    for (int d = 128; d > 0; d >>= 1) {
        if (k < d) red[k] += red[k + d];
        __syncthreads();
    }
    if (k == 0) g_bc[j] = red[0] + ((j < 128) ? b_lin[j] : 0.f);
}

// ---------------- GEMM: bf16 split mma.sync, M=30000 N=256 Kv=768 -------------
#define GSTEPS 48

__global__ __launch_bounds__(256) void gemm_mma_kernel(const float* __restrict__ x) {
    __shared__ __align__(16) char As[2][128 * 48];   // 128 rows x 16 bf16 (pitch 48B)
    __shared__ __align__(16) char Bs[2][16 * 272];   // 16 k-rows x 128 bf16 (pitch 272B)
    __shared__ float bcs[128];

    int tid = threadIdx.x;
    int lane = tid & 31, wid = tid >> 5;
    int wm = wid >> 2, wn = wid & 3;                  // 2 x 4 warp grid
    int row0 = blockIdx.y * 128, col0 = blockIdx.x * 128;

    if (tid < 128) bcs[tid] = g_bc[col0 + tid];

    int arow = tid >> 1, ac8 = (tid & 1) * 8;
    bool avalid = (row0 + arow) < N_NODES;
    const float* axp = x + (size_t)(row0 + arow) * 256 + ac8;
    int bkrow = tid >> 4, bnc = (tid & 15) * 8;
    const __nv_bfloat16* bwp = g_Wb + bkrow * 256 + col0 + bnc;

    float4 fa0, fa1; uint4 fb;

    // prefetch stage 0
    {
        if (avalid) { fa0 = *(const float4*)(axp); fa1 = *(const float4*)(axp + 4); }
        else { fa0 = make_float4(0,0,0,0); fa1 = fa0; }
        fb = *(const uint4*)(bwp);
    }
    // store stage 0
    {
        union { __nv_bfloat16 h[8]; uint4 u; } pk;
        float v[8] = {fa0.x,fa0.y,fa0.z,fa0.w,fa1.x,fa1.y,fa1.z,fa1.w};
        #pragma unroll
        for (int i = 0; i < 8; i++) pk.h[i] = __float2bfloat16(v[i]);   // seg0 = hi
        *(uint4*)(As[0] + arow * 48 + ac8 * 2) = pk.u;
        *(uint4*)(Bs[0] + bkrow * 272 + bnc * 2) = fb;
    }
    __syncthreads();

    float acc[4][4][4];
    #pragma unroll
    for (int a = 0; a < 4; a++)
        #pragma unroll
        for (int b = 0; b < 4; b++)
            #pragma unroll
            for (int c = 0; c < 4; c++) acc[a][b][c] = 0.f;

    for (int s = 0; s < GSTEPS; s++) {
        int cb = s & 1;
        // issue next-stage global loads (latency hidden behind compute)
        if (s + 1 < GSTEPS) {
            int sn = s + 1;
            int rk0 = (sn & 15) * 16;
            if (avalid) { fa0 = *(const float4*)(axp + rk0); fa1 = *(const float4*)(axp + rk0 + 4); }
            else { fa0 = make_float4(0,0,0,0); fa1 = fa0; }
            fb = *(const uint4*)(bwp + sn * 16 * 256);
        }

        // ---- compute stage s
        const char* Ab = As[cb];
        const char* Bb = Bs[cb];
        uint32_t afr[4][4];
        #pragma unroll
        for (int im = 0; im < 4; im++) {
            const char* p = Ab + (wm * 64 + im * 16 + (lane & 15)) * 48 + (lane >> 4) * 16;
            unsigned ad = (unsigned)__cvta_generic_to_shared(p);
            asm volatile("ldmatrix.sync.aligned.m8n8.x4.shared.b16 {%0,%1,%2,%3}, [%4];"
                : "=r"(afr[im][0]), "=r"(afr[im][1]), "=r"(afr[im][2]), "=r"(afr[im][3]) : "r"(ad));
        }
        uint32_t bfr[4][2];
        #pragma unroll
        for (int half = 0; half < 2; half++) {
            const char* p = Bb + (lane & 15) * 272 + (wn * 32 + half * 16 + (lane >> 4) * 8) * 2;
            unsigned ad = (unsigned)__cvta_generic_to_shared(p);
            uint32_t r0, r1, r2, r3;
            asm volatile("ldmatrix.sync.aligned.m8n8.x4.trans.shared.b16 {%0,%1,%2,%3}, [%4];"
                : "=r"(r0), "=r"(r1), "=r"(r2), "=r"(r3) : "r"(ad));
            bfr[half*2][0] = r0; bfr[half*2][1] = r1;
            bfr[half*2+1][0] = r2; bfr[half*2+1][1] = r3;
        }
        #pragma unroll
        for (int im = 0; im < 4; im++)
            #pragma unroll
            for (int in = 0; in < 4; in++) {
                asm volatile(
                    "mma.sync.aligned.m16n8k16.row.col.f32.bf16.bf16.f32 "
                    "{%0,%1,%2,%3}, {%4,%5,%6,%7}, {%8,%9}, {%0,%1,%2,%3};"
                    : "+f"(acc[im][in][0]), "+f"(acc[im][in][1]),
                      "+f"(acc[im][in][2]), "+f"(acc[im][in][3])
                    : "r"(afr[im][0]), "r"(afr[im][1]), "r"(afr[im][2]), "r"(afr[im][3]),
                      "r"(bfr[in][0]), "r"(bfr[in][1]));
            }

        // ---- store next stage
        if (s + 1 < GSTEPS) {
            int seg = (s + 1) >> 4;
            union { __nv_bfloat16 h[8]; uint4 u; } pk;
            float v[8] = {fa0.x,fa0.y,fa0.z,fa0.w,fa1.x,fa1.y,fa1.z,fa1.w};
            #pragma unroll
            for (int i = 0; i < 8; i++) {
                __nv_bfloat16 hb = __float2bfloat16(v[i]);
                if (seg == 2) hb = __float2bfloat16(v[i] - __bfloat162float(hb));
                pk.h[i] = hb;
            }
            *(uint4*)(As[cb ^ 1] + arow * 48 + ac8 * 2) = pk.u;
            *(uint4*)(Bs[cb ^ 1] + bkrow * 272 + bnc * 2) = fb;
        }
        __syncthreads();
    }

    // ---- epilogue
    #pragma unroll
    for (int im = 0; im < 4; im++) {
        int r = row0 + wm * 64 + im * 16 + (lane >> 2);
        #pragma unroll
        for (int in = 0; in < 4; in++) {
            int crel = wn * 32 + in * 8 + (lane & 3) * 2;
            int c = col0 + crel;
            if (r < N_NODES) {
                float2 v0 = make_float2(acc[im][in][0] + bcs[crel],
                                        acc[im][in][1] + bcs[crel + 1]);
                *(float2*)&g_C[(size_t)r * 256 + c] = v0;
            }
            if (r + 8 < N_NODES) {
                float2 v1 = make_float2(acc[im][in][2] + bcs[crel],
                                        acc[im][in][3] + bcs[crel + 1]);
                *(float2*)&g_C[(size_t)(r + 8) * 256 + c] = v1;
            }
        }
    }
}

// ---------------- per-node attention dots --------------------------------------
__global__ void dots_kernel(const float* __restrict__ att) {
    int w = (blockIdx.x * blockDim.x + threadIdx.x) >> 5;
    int lane = threadIdx.x & 31;
    if (w >= N_NODES) return;
    #pragma unroll
    for (int h = 0; h < HEADS; h++) {
        float xv = g_C[(size_t)w * 256 + 128 + h * 32 + lane];
        float si = xv * att[h * 64 + lane];
        float sj = xv * att[h * 64 + 32 + lane];
        #pragma unroll
        for (int d = 16; d > 0; d >>= 1) {
            si += __shfl_xor_sync(0xffffffffu, si, d);
            sj += __shfl_xor_sync(0xffffffffu, sj, d);
        }
        if (lane == 0) { g_si[w * 4 + h] = si; g_sj[w * 4 + h] = sj; }
    }
}

// ---------------- CSR build ------------------------------------------------------
__global__ void deg_kernel(const int* __restrict__ dst) {
    int e = blockIdx.x * blockDim.x + threadIdx.x;
    if (e >= T_EDGES) return;
    int d = (e < E_EDGES) ? dst[e] : (e - E_EDGES);
    atomicAdd(&g_deg[d], 1);
}

__global__ void scan_kernel() {
    __shared__ int wsum[32];
    int tid = threadIdx.x;
    int lane = tid & 31, wrp = tid >> 5;
    int carry = 0;
    const int CH = (N_NODES + 1023) / 1024;
    for (int c = 0; c < CH; c++) {
        int i = c * 1024 + tid;
        int v = (i < N_NODES) ? g_deg[i] : 0;
        int incl = v;
        #pragma unroll
        for (int d = 1; d < 32; d <<= 1) {
            int t = __shfl_up_sync(0xffffffffu, incl, d);
            if (lane >= d) incl += t;
        }
        if (lane == 31) wsum[wrp] = incl;
        __syncthreads();
        if (wrp == 0) {
            int wv = wsum[lane];
            #pragma unroll
            for (int d = 1; d < 32; d <<= 1) {
                int t = __shfl_up_sync(0xffffffffu, wv, d);
                if (lane >= d) wv += t;
            }
            wsum[lane] = wv;
        }
        __syncthreads();
        int base = (wrp > 0) ? wsum[wrp - 1] : 0;
        if (i < N_NODES) g_off[i] = carry + base + incl - v;
        carry += wsum[31];
        __syncthreads();
    }
    if (tid == 0) g_off[N_NODES] = carry;
}

__global__ void curcopy_kernel() {
    int n = blockIdx.x * blockDim.x + threadIdx.x;
    if (n < N_NODES) g_cur[n] = g_off[n];
}

__global__ void scatter_kernel(const int* __restrict__ src,
                               const int* __restrict__ dst) {
    int e = blockIdx.x * blockDim.x + threadIdx.x;
    if (e >= T_EDGES) return;
    int s, d;
    if (e < E_EDGES) { s = src[e]; d = dst[e]; }
    else             { s = d = e - E_EDGES; }
    int pos = atomicAdd(&g_cur[d], 1);
    g_srcp[pos] = s;
}

// ---------------- segment softmax + aggregation (warp per node-head) ------------
__global__ __launch_bounds__(256) void aggr_kernel(const float* __restrict__ b_gat) {
    int gw = (blockIdx.x * 256 + threadIdx.x) >> 5;
    int lane = threadIdx.x & 31;
    if (gw >= N_NODES * HEADS) return;
    int n = gw >> 2, h = gw & 3;
    int beg = g_off[n], end = g_off[n + 1];
    float si = g_si[n * 4 + h];

    float m = -1e30f;
    for (int j = beg + lane; j < end; j += 32) {
        int s = g_srcp[j];
        float a = si + g_sj[s * 4 + h];
        a = (a >= 0.f) ? a : NEG_SLOPE * a;
        m = fmaxf(m, a);
    }
    #pragma unroll
    for (int d = 16; d > 0; d >>= 1)
        m = fmaxf(m, __shfl_xor_sync(0xffffffffu, m, d));

    float den = 0.f, acc = 0.f;
    for (int j = beg; j < end; j++) {
        int s = g_srcp[j];
        float a = si + g_sj[s * 4 + h];
        a = (a >= 0.f) ? a : NEG_SLOPE * a;
        float e = __expf(a - m);
        acc += e * g_C[(size_t)s * 256 + 128 + h * 32 + lane];
        den += e;
    }
    float r = acc / (den + 1e-16f) + b_gat[h * 32 + lane];
    g_gat[(size_t)n * HH + h * 32 + lane] = fmaxf(r, 0.f);
}

// ---------------- capsule + routing (warp per node) ------------------------------
#define CWARPS 8
#define CAP_SMEM_FLOATS (24576 + 512 + 16 + CWARPS*264 + CWARPS*128 + CWARPS*96)

__global__ __launch_bounds__(CWARPS * 32, 1)
void capsule_kernel(const float* __restrict__ Wp, const float* __restrict__ bp,
                    const float* __restrict__ route_w, const int* __restrict__ y,
                    float* __restrict__ out) {
    extern __shared__ float sh[];
    float4* rw4 = (float4*)sh;             // 6144 float4 = 24576 floats
    float* wps = sh + 24576;               // 512
    float* bps = wps + 512;                // 16
    float* xcs = bps + 16;                 // CWARPS * 264
    float* us  = xcs + CWARPS * 264;       // CWARPS * 128
    float* lgs = us  + CWARPS * 128;       // CWARPS * 96
    __shared__ float blockLoss;

    int tid = threadIdx.x, lane = tid & 31, w = tid >> 5;

    // repack route_w: rw4[(pair*2+kq)*32 + lane] = {w[k..k+3] at o=lane}, k=4*kq
    for (int i4 = tid; i4 < 6144; i4 += CWARPS * 32) {
        int pair = i4 >> 6;
        int rem = i4 & 63;
        int kq = rem >> 5, ln = rem & 31;
        int base = (pair * 8 + kq * 4) * 32 + ln;
        rw4[i4] = make_float4(route_w[base], route_w[base + 32],
                              route_w[base + 64], route_w[base + 96]);
    }
    for (int i = tid; i < 512; i += CWARPS * 32) wps[i] = Wp[i];
    if (tid < 16) bps[tid] = bp[tid];
    if (tid == 0) blockLoss = 0.f;
    __syncthreads();

    float* xcw = xcs + w * 264;
    float* uw  = us  + w * 128;
    float* lgw = lgs + w * 96;

    int gw = blockIdx.x * CWARPS + w;
    int nstride = gridDim.x * CWARPS;

    for (int n = gw; n < N_NODES; n += nstride) {
        #pragma unroll
        for (int r = 0; r < 8; r++) {
            float v = (r < 4)
                ? g_gat[(size_t)n * HH + r * 32 + lane]
                : fmaxf(g_C[(size_t)n * 256 + (r - 4) * 32 + lane], 0.f);
            xcw[r * 33 + lane] = v;
        }
        __syncwarp();

        #pragma unroll
        for (int q = 0; q < 4; q++) {
            int idx = lane + 32 * q;
            int c = idx >> 6, r = (idx >> 3) & 7, o = idx & 7;
            float acc = bps[c * 8 + o];
            #pragma unroll
            for (int hh = 0; hh < 32; hh++)
                acc += xcw[r * 33 + hh] * wps[(c * 32 + hh) * 8 + o];
            float t = acc * acc;
            t += __shfl_xor_sync(0xffffffffu, t, 1);
            t += __shfl_xor_sync(0xffffffffu, t, 2);
            t += __shfl_xor_sync(0xffffffffu, t, 4);
            float uv = acc * t / ((1.f + t) * sqrtf(t));
            uw[idx] = uv;
        }
        __syncwarp();

        float pr[96];
        #pragma unroll
        for (int rr = 0; rr < 16; rr++) {
            float u0 = uw[rr*8+0], u1 = uw[rr*8+1], u2 = uw[rr*8+2], u3 = uw[rr*8+3];
            float u4 = uw[rr*8+4], u5 = uw[rr*8+5], u6 = uw[rr*8+6], u7 = uw[rr*8+7];
            #pragma unroll
            for (int c2 = 0; c2 < 6; c2++) {
                int pair = c2 * 16 + rr;
                float4 f0 = rw4[(pair * 2 + 0) * 32 + lane];
                float4 f1 = rw4[(pair * 2 + 1) * 32 + lane];
                pr[c2 * 16 + rr] =
                    u0 * f0.x + u1 * f0.y + u2 * f0.z + u3 * f0.w +
                    u4 * f1.x + u5 * f1.y + u6 * f1.z + u7 * f1.w;
            }
        }

        for (int p = lane; p < 96; p += 32) lgw[p] = 0.f;
        __syncwarp();

        float vout[6], normc[6];
        for (int it = 0; it < 3; it++) {
            #pragma unroll
            for (int c = 0; c < 6; c++) {
                float lg[16];
                #pragma unroll
                for (int r = 0; r < 16; r++) lg[r] = lgw[c * 16 + r];
                float mx = lg[0];
                #pragma unroll
                for (int r = 1; r < 16; r++) mx = fmaxf(mx, lg[r]);
                float sm = 0.f;
                #pragma unroll
                for (int r = 0; r < 16; r++) { lg[r] = __expf(lg[r] - mx); sm += lg[r]; }
                float inv = 1.f / sm;
                float vv = 0.f;
                #pragma unroll
                for (int r = 0; r < 16; r++) vv += lg[r] * pr[c * 16 + r];
                vv *= inv;
                float t = vv * vv;
                t += __shfl_xor_sync(0xffffffffu, t, 1);
                t += __shfl_xor_sync(0xffffffffu, t, 2);
                t += __shfl_xor_sync(0xffffffffu, t, 4);
                t += __shfl_xor_sync(0xffffffffu, t, 8);
                t += __shfl_xor_sync(0xffffffffu, t, 16);
                float sc = t / ((1.f + t) * sqrtf(t));
                vout[c]  = vv * sc;
                normc[c] = t / (1.f + t);
            }
            if (it < 2) {
                #pragma unroll
                for (int c = 0; c < 6; c++) {
                    #pragma unroll
                    for (int r = 0; r < 16; r++) {
                        float t = pr[c * 16 + r] * vout[c];
                        t += __shfl_xor_sync(0xffffffffu, t, 1);
                        t += __shfl_xor_sync(0xffffffffu, t, 2);
                        t += __shfl_xor_sync(0xffffffffu, t, 4);
                        t += __shfl_xor_sync(0xffffffffu, t, 8);
                        t += __shfl_xor_sync(0xffffffffu, t, 16);
                        if (lane == 0) lgw[c * 16 + r] += t;
                    }
                }
                __syncwarp();
            }
        }

        #pragma unroll
        for (int c = 0; c < 6; c++)
            out[OUT_OFF_FEAT + (size_t)n * (NUM_LABEL * HDIM) + c * 32 + lane] = vout[c];

        if (lane == 0) {
            float mx = normc[0];
            #pragma unroll
            for (int c = 1; c < 6; c++) mx = fmaxf(mx, normc[c]);
            float sm = 0.f;
            #pragma unroll
            for (int c = 0; c < 6; c++) sm += __expf(normc[c] - mx);
            float lse = mx + logf(sm);
            int yv = y[n];
            float sel = 0.f;
            #pragma unroll
            for (int c = 0; c < 6; c++) {
                out[(size_t)n * 6 + c] = normc[c];
                if (c == yv) sel = normc[c];
            }
            atomicAdd(&blockLoss, lse - sel);
        }
    }
    __syncthreads();
    if (tid == 0) atomicAdd(&out[OUT_OFF_LOSS], blockLoss / (float)N_NODES);
}

// ---------------- launch ---------------------------------------------------------
extern "C" void kernel_launch(void* const* d_in, const int* in_sizes, int n_in,
                              void* d_out, int out_size) {
    const float* x       = (const float*)d_in[0];
    const float* gamma   = (const float*)d_in[1];
    const float* beta    = (const float*)d_in[2];
    const float* W_lin   = (const float*)d_in[3];
    const float* b_lin   = (const float*)d_in[4];
    const float* W_gat   = (const float*)d_in[5];
    const float* att     = (const float*)d_in[6];
    const float* b_gat   = (const float*)d_in[7];
    const float* Wp      = (const float*)d_in[8];
    const float* bp      = (const float*)d_in[9];
    const float* route_w = (const float*)d_in[10];
    const int*   eidx    = (const int*)d_in[11];
    const int*   y       = (const int*)d_in[12];
    float* out = (float*)d_out;

    const int* src = eidx;
    const int* dst = eidx + E_EDGES;

    init_kernel<<<(2 * FDIM + N_NODES + 256) / 256, 256>>>(out);
    bn_stats_kernel<<<240, 256>>>(x);
    bn_fin_kernel<<<1, 256>>>(gamma, beta);
    fold_w_kernel<<<256, 256>>>(W_lin, W_gat);
    fold_b_kernel<<<256, 256>>>(W_lin, W_gat, b_lin);

    gemm_mma_kernel<<<dim3(2, (N_NODES + 127) / 128), 256>>>(x);

    dots_kernel<<<(N_NODES * 32 + 255) / 256, 256>>>(att);
    deg_kernel<<<(T_EDGES + 255) / 256, 256>>>(dst);
    scan_kernel<<<1, 1024>>>();
    curcopy_kernel<<<(N_NODES + 255) / 256, 256>>>();
    scatter_kernel<<<(T_EDGES + 255) / 256, 256>>>(src, dst);
    aggr_kernel<<<(N_NODES * HEADS + 7) / 8, 256>>>(b_gat);

    static const size_t cap_smem = (size_t)CAP_SMEM_FLOATS * sizeof(float);
    cudaFuncSetAttribute(capsule_kernel,
                         cudaFuncAttributeMaxDynamicSharedMemorySize,
                         (int)cap_smem);
    capsule_kernel<<<148, CWARPS * 32, cap_smem>>>(Wp, bp, route_w, y, out);
}